// round 2
// baseline (speedup 1.0000x reference)
#include <cuda_runtime.h>
#include <cstdint>

#define HIDDEN    450
#define DEPTH     6
#define ATOM_FDIM 35
#define BOND_FDIM 5
#define MAX_NB    15
#define N_ATOMS   20000
#define N_BONDS   40000
#define N_MESS    16000
#define N_MOLS    1000
#define BOND_IN   (ATOM_FDIM + BOND_FDIM)   // 40
#define AIN       (ATOM_FDIM + HIDDEN)      // 485

// ---------------- scratch (device globals; no runtime allocation) ----------
__device__ float g_binput[(size_t)N_BONDS * HIDDEN];
__device__ float g_msg   [(size_t)N_BONDS * HIDDEN];
__device__ float g_nei   [(size_t)N_BONDS * HIDDEN];
__device__ float g_ain   [(size_t)N_ATOMS * AIN];
__device__ float g_hid   [(size_t)N_ATOMS * HIDDEN];
__device__ float g_cnt   [N_MOLS];

// ---------------- tiled fp32 NT GEMM: C[m,n] = sum_k A[m,k] * W[n,k] --------
// MODE 0: C = acc
// MODE 1: C = relu(acc + add[m*N+n])
// MODE 2: C = relu(acc + add[n])
#define BM 128
#define BN 64
#define BK 16

template <int MODE>
__global__ __launch_bounds__(128)
void gemm_nt(const float* __restrict__ A, const float* __restrict__ W,
             const float* __restrict__ add, float* __restrict__ C,
             int M, int N, int K)
{
    __shared__ float sA[BK][BM];
    __shared__ float sB[BK][BN];

    const int bm  = blockIdx.y * BM;
    const int bn  = blockIdx.x * BN;
    const int tid = threadIdx.x;          // 128 threads
    const int tx  = tid & 7;              // n direction
    const int ty  = tid >> 3;             // m direction

    float acc[8][8];
#pragma unroll
    for (int i = 0; i < 8; i++)
#pragma unroll
        for (int j = 0; j < 8; j++) acc[i][j] = 0.f;

    for (int k0 = 0; k0 < K; k0 += BK) {
        // stage global loads into registers — SCALAR loads (row pitches 450/485
        // floats are not 16B-aligned, LDG.128 would trap)
        float av[4][4], wv[2][4];
#pragma unroll
        for (int it = 0; it < 4; it++) {
            int idx = tid + it * 128;
            int r = idx >> 2, cg = (idx & 3) << 2;
            int m = bm + r;
            const float* p = A + (size_t)m * K + k0 + cg;
#pragma unroll
            for (int q = 0; q < 4; q++) {
                int k = k0 + cg + q;
                av[it][q] = (m < M && k < K) ? p[q] : 0.f;
            }
        }
#pragma unroll
        for (int it = 0; it < 2; it++) {
            int idx = tid + it * 128;
            int r = idx >> 2, cg = (idx & 3) << 2;
            int n = bn + r;
            const float* p = W + (size_t)n * K + k0 + cg;
#pragma unroll
            for (int q = 0; q < 4; q++) {
                int k = k0 + cg + q;
                wv[it][q] = (n < N && k < K) ? p[q] : 0.f;
            }
        }
        __syncthreads();   // previous tile's compute must be done
#pragma unroll
        for (int it = 0; it < 4; it++) {
            int idx = tid + it * 128;
            int r = idx >> 2, cg = (idx & 3) << 2;
#pragma unroll
            for (int q = 0; q < 4; q++) sA[cg + q][r] = av[it][q];
        }
#pragma unroll
        for (int it = 0; it < 2; it++) {
            int idx = tid + it * 128;
            int r = idx >> 2, cg = (idx & 3) << 2;
#pragma unroll
            for (int q = 0; q < 4; q++) sB[cg + q][r] = wv[it][q];
        }
        __syncthreads();

#pragma unroll
        for (int k = 0; k < BK; k++) {
            float a_[8], b_[8];
            *(float4*)&a_[0] = *(const float4*)&sA[k][ty * 8];
            *(float4*)&a_[4] = *(const float4*)&sA[k][ty * 8 + 4];
            *(float4*)&b_[0] = *(const float4*)&sB[k][tx * 8];
            *(float4*)&b_[4] = *(const float4*)&sB[k][tx * 8 + 4];
#pragma unroll
            for (int i = 0; i < 8; i++)
#pragma unroll
                for (int j = 0; j < 8; j++) acc[i][j] += a_[i] * b_[j];
        }
    }

#pragma unroll
    for (int i = 0; i < 8; i++) {
        int m = bm + ty * 8 + i;
        if (m >= M) break;
#pragma unroll
        for (int j = 0; j < 8; j++) {
            int n = bn + tx * 8 + j;
            if (n < N) {
                float v = acc[i][j];
                if (MODE == 1) v = fmaxf(v + add[(size_t)m * N + n], 0.f);
                else if (MODE == 2) v = fmaxf(v + add[n], 0.f);
                C[(size_t)m * N + n] = v;
            }
        }
    }
}

// ---------------- elementwise relu ------------------------------------------
__global__ void relu_copy(const float* __restrict__ x, float* __restrict__ y, int n)
{
    int i = blockIdx.x * blockDim.x + threadIdx.x;
    if (i < n) y[i] = fmaxf(x[i], 0.f);
}

// ---------------- 15-neighbor gather-sum ------------------------------------
__global__ void gather_bonds(const int* __restrict__ bgraph,
                             const float* __restrict__ tree,
                             const float* __restrict__ gmsg,
                             float* __restrict__ nei)
{
    int b = blockIdx.x;
    __shared__ const float* ptrs[MAX_NB];
    int t = threadIdx.x;
    if (t < MAX_NB) {
        int j = bgraph[(size_t)b * MAX_NB + t];
        ptrs[t] = (j < N_MESS) ? (tree + (size_t)j * HIDDEN)
                               : (gmsg + (size_t)(j - N_MESS) * HIDDEN);
    }
    __syncthreads();
    for (int h = t; h < HIDDEN; h += blockDim.x) {
        float s = 0.f;
#pragma unroll
        for (int k = 0; k < MAX_NB; k++) s += ptrs[k][h];
        nei[(size_t)b * HIDDEN + h] = s;
    }
}

// ---------------- atom gather + concat --------------------------------------
__global__ void gather_atoms(const int* __restrict__ agraph,
                             const float* __restrict__ fatoms,
                             const float* __restrict__ tree,
                             const float* __restrict__ gmsg,
                             float* __restrict__ ain)
{
    int a = blockIdx.x;
    __shared__ const float* ptrs[MAX_NB];
    int t = threadIdx.x;
    if (t < MAX_NB) {
        int j = agraph[(size_t)a * MAX_NB + t];
        ptrs[t] = (j < N_MESS) ? (tree + (size_t)j * HIDDEN)
                               : (gmsg + (size_t)(j - N_MESS) * HIDDEN);
    }
    __syncthreads();
    float* dst = ain + (size_t)a * AIN;
    for (int h = t; h < ATOM_FDIM; h += blockDim.x)
        dst[h] = fatoms[(size_t)a * ATOM_FDIM + h];
    for (int h = t; h < HIDDEN; h += blockDim.x) {
        float s = 0.f;
#pragma unroll
        for (int k = 0; k < MAX_NB; k++) s += ptrs[k][h];
        dst[ATOM_FDIM + h] = s;
    }
}

// ---------------- segment mean ----------------------------------------------
__global__ void zero_out(float* __restrict__ out, float* __restrict__ cnt)
{
    int i = blockIdx.x * blockDim.x + threadIdx.x;
    if (i < N_MOLS * HIDDEN) out[i] = 0.f;
    if (i < N_MOLS) cnt[i] = 0.f;
}

__global__ void count_mols(const int* __restrict__ mol_ids, float* __restrict__ cnt)
{
    int a = blockIdx.x * blockDim.x + threadIdx.x;
    if (a < N_ATOMS) atomicAdd(&cnt[mol_ids[a]], 1.f);
}

__global__ void accum_mols(const float* __restrict__ hid,
                           const int* __restrict__ mol_ids,
                           float* __restrict__ out)
{
    int a = blockIdx.x;
    int m = mol_ids[a];
    for (int h = threadIdx.x; h < HIDDEN; h += blockDim.x)
        atomicAdd(&out[(size_t)m * HIDDEN + h], hid[(size_t)a * HIDDEN + h]);
}

__global__ void divide_mols(float* __restrict__ out, const float* __restrict__ cnt)
{
    int m = blockIdx.x;
    float inv = 1.f / cnt[m];
    for (int h = threadIdx.x; h < HIDDEN; h += blockDim.x)
        out[(size_t)m * HIDDEN + h] *= inv;
}

// ---------------- launch ------------------------------------------------------
extern "C" void kernel_launch(void* const* d_in, const int* in_sizes, int n_in,
                              void* d_out, int out_size)
{
    const float *fatoms = 0, *fbonds = 0, *tree = 0, *W_i = 0, *W_h = 0, *W_o = 0, *b_o = 0;
    const int *agraph = 0, *bgraph = 0, *mol_ids = 0;
    for (int i = 0; i < n_in; i++) {
        switch (in_sizes[i]) {
            case N_ATOMS * ATOM_FDIM: fatoms  = (const float*)d_in[i]; break;
            case N_BONDS * BOND_IN:   fbonds  = (const float*)d_in[i]; break;
            case N_ATOMS * MAX_NB:    agraph  = (const int*)  d_in[i]; break;
            case N_BONDS * MAX_NB:    bgraph  = (const int*)  d_in[i]; break;
            case N_ATOMS:             mol_ids = (const int*)  d_in[i]; break;
            case N_MESS * HIDDEN:     tree    = (const float*)d_in[i]; break;
            case HIDDEN * BOND_IN:    W_i     = (const float*)d_in[i]; break;
            case HIDDEN * HIDDEN:     W_h     = (const float*)d_in[i]; break;
            case HIDDEN * AIN:        W_o     = (const float*)d_in[i]; break;
            case HIDDEN:              b_o     = (const float*)d_in[i]; break;
            default: break;
        }
    }
    float* out = (float*)d_out;

    static float *p_binput = 0, *p_msg = 0, *p_nei = 0, *p_ain = 0, *p_hid = 0, *p_cnt = 0;
    if (!p_binput) {
        cudaGetSymbolAddress((void**)&p_binput, g_binput);
        cudaGetSymbolAddress((void**)&p_msg,    g_msg);
        cudaGetSymbolAddress((void**)&p_nei,    g_nei);
        cudaGetSymbolAddress((void**)&p_ain,    g_ain);
        cudaGetSymbolAddress((void**)&p_hid,    g_hid);
        cudaGetSymbolAddress((void**)&p_cnt,    g_cnt);
    }

    dim3 gB((HIDDEN + BN - 1) / BN, (N_BONDS + BM - 1) / BM);
    dim3 gA((HIDDEN + BN - 1) / BN, (N_ATOMS + BM - 1) / BM);

    gemm_nt<0><<<gB, 128>>>(fbonds, W_i, nullptr, p_binput, N_BONDS, HIDDEN, BOND_IN);
    relu_copy<<<(N_BONDS * HIDDEN + 255) / 256, 256>>>(p_binput, p_msg, N_BONDS * HIDDEN);

    for (int it = 0; it < DEPTH - 1; it++) {
        gather_bonds<<<N_BONDS, 256>>>(bgraph, tree, p_msg, p_nei);
        gemm_nt<1><<<gB, 128>>>(p_nei, W_h, p_binput, p_msg, N_BONDS, HIDDEN, HIDDEN);
    }

    gather_atoms<<<N_ATOMS, 256>>>(agraph, fatoms, tree, p_msg, p_ain);
    gemm_nt<2><<<gA, 128>>>(p_ain, W_o, b_o, p_hid, N_ATOMS, HIDDEN, AIN);

    zero_out<<<(N_MOLS * HIDDEN + 255) / 256, 256>>>(out, p_cnt);
    count_mols<<<(N_ATOMS + 255) / 256, 256>>>(mol_ids, p_cnt);
    accum_mols<<<N_ATOMS, 128>>>(p_hid, mol_ids, out);
    divide_mols<<<N_MOLS, 128>>>(out, p_cnt);
}

// round 3
// speedup vs baseline: 1.1299x; 1.1299x over previous
#include <cuda_runtime.h>
#include <cstdint>

#define HIDDEN    450
#define DEPTH     6
#define ATOM_FDIM 35
#define BOND_FDIM 5
#define MAX_NB    15
#define N_ATOMS   20000
#define N_BONDS   40000
#define N_MESS    16000
#define N_MOLS    1000
#define BOND_IN   (ATOM_FDIM + BOND_FDIM)   // 40
#define AIN       (ATOM_FDIM + HIDDEN)      // 485

// ---------------- scratch (device globals; no runtime allocation) ----------
__device__ float g_binput[(size_t)N_BONDS * HIDDEN];
__device__ float g_msg   [(size_t)N_BONDS * HIDDEN];
__device__ float g_nei   [(size_t)N_BONDS * HIDDEN];
__device__ float g_ain   [(size_t)N_ATOMS * AIN];
__device__ float g_hid   [(size_t)N_ATOMS * HIDDEN];
__device__ float g_cnt   [N_MOLS];

// ---------------- pipelined fp32 NT GEMM: C[m,n] = sum_k A[m,k]*W[n,k] ------
// MODE 0: C = acc, C2 = relu(acc)        (binput + graph_message fused)
// MODE 1: C = relu(acc + add[m*N+n])     (message update)
// MODE 2: C = relu(acc + add[n])         (output layer with bias)
#define BM 128
#define BN 128
#define BK 16
#define SPITCH 132   // padded smem row pitch (16B-aligned, low STS conflicts)

template <int MODE>
__global__ __launch_bounds__(256, 2)
void gemm_nt(const float* __restrict__ A, const float* __restrict__ W,
             const float* __restrict__ add, float* __restrict__ C,
             float* __restrict__ C2, int M, int N, int K)
{
    __shared__ float sA[2][BK * SPITCH];
    __shared__ float sB[2][BK * SPITCH];

    const int bm  = blockIdx.y * BM;
    const int bn  = blockIdx.x * BN;
    const int tid = threadIdx.x;          // 256 threads
    const int tx  = tid & 15;             // n direction (16)
    const int ty  = tid >> 4;             // m direction (16)

    float acc[8][8];
#pragma unroll
    for (int i = 0; i < 8; i++)
#pragma unroll
        for (int j = 0; j < 8; j++) acc[i][j] = 0.f;

    const int ntiles = (K + BK - 1) / BK;
    float ar[8], br[8];

    // staging map: element idx = tid + i*256 ; r = idx/16 (row), kk = idx%16
    // -> per-LDG a warp covers 2 rows x 16 consecutive k : 4 sectors/instr.
    const int r_  = tid >> 4;             // 0..15 base handled via idx below

    // ---- prologue: load tile 0 ----
#pragma unroll
    for (int i = 0; i < 8; i++) {
        int idx = tid + i * 256;
        int r = idx >> 4, kk = idx & 15;
        int m = bm + r, k = kk;
        ar[i] = (m < M && k < K) ? A[(size_t)m * K + k] : 0.f;
        int n = bn + r;
        br[i] = (n < N && k < K) ? W[(size_t)n * K + k] : 0.f;
    }
#pragma unroll
    for (int i = 0; i < 8; i++) {
        int idx = tid + i * 256;
        int r = idx >> 4, kk = idx & 15;
        sA[0][kk * SPITCH + r] = ar[i];
        sB[0][kk * SPITCH + r] = br[i];
    }
    __syncthreads();

    int buf = 0;
    (void)r_;
    for (int t = 0; t < ntiles; t++) {
        // ---- issue next tile's global loads early ----
        if (t + 1 < ntiles) {
            int k0 = (t + 1) * BK;
#pragma unroll
            for (int i = 0; i < 8; i++) {
                int idx = tid + i * 256;
                int r = idx >> 4, kk = idx & 15;
                int m = bm + r, k = k0 + kk;
                ar[i] = (m < M && k < K) ? A[(size_t)m * K + k] : 0.f;
                int n = bn + r;
                br[i] = (n < N && k < K) ? W[(size_t)n * K + k] : 0.f;
            }
        }
        // ---- compute on current buffer ----
        const float* pa = sA[buf];
        const float* pb = sB[buf];
#pragma unroll
        for (int kk = 0; kk < BK; kk++) {
            float a_[8], b_[8];
            *(float4*)&a_[0] = *(const float4*)&pa[kk * SPITCH + ty * 8];
            *(float4*)&a_[4] = *(const float4*)&pa[kk * SPITCH + ty * 8 + 4];
            *(float4*)&b_[0] = *(const float4*)&pb[kk * SPITCH + tx * 8];
            *(float4*)&b_[4] = *(const float4*)&pb[kk * SPITCH + tx * 8 + 4];
#pragma unroll
            for (int i = 0; i < 8; i++)
#pragma unroll
                for (int j = 0; j < 8; j++) acc[i][j] += a_[i] * b_[j];
        }
        // ---- stash next tile into the other buffer ----
        if (t + 1 < ntiles) {
            int nb = buf ^ 1;
#pragma unroll
            for (int i = 0; i < 8; i++) {
                int idx = tid + i * 256;
                int r = idx >> 4, kk = idx & 15;
                sA[nb][kk * SPITCH + r] = ar[i];
                sB[nb][kk * SPITCH + r] = br[i];
            }
            __syncthreads();
            buf = nb;
        }
    }

    // ---- epilogue ----
#pragma unroll
    for (int i = 0; i < 8; i++) {
        int m = bm + ty * 8 + i;
        if (m >= M) break;
#pragma unroll
        for (int j = 0; j < 8; j++) {
            int n = bn + tx * 8 + j;
            if (n < N) {
                float v = acc[i][j];
                if (MODE == 0) {
                    C [(size_t)m * N + n] = v;
                    C2[(size_t)m * N + n] = fmaxf(v, 0.f);
                } else if (MODE == 1) {
                    C[(size_t)m * N + n] = fmaxf(v + add[(size_t)m * N + n], 0.f);
                } else {
                    C[(size_t)m * N + n] = fmaxf(v + add[n], 0.f);
                }
            }
        }
    }
}

// ---------------- 15-neighbor gather-sum ------------------------------------
__global__ void gather_bonds(const int* __restrict__ bgraph,
                             const float* __restrict__ tree,
                             const float* __restrict__ gmsg,
                             float* __restrict__ nei)
{
    int b = blockIdx.x;
    __shared__ const float* ptrs[MAX_NB];
    int t = threadIdx.x;
    if (t < MAX_NB) {
        int j = bgraph[(size_t)b * MAX_NB + t];
        ptrs[t] = (j < N_MESS) ? (tree + (size_t)j * HIDDEN)
                               : (gmsg + (size_t)(j - N_MESS) * HIDDEN);
    }
    __syncthreads();
    for (int h = t; h < HIDDEN; h += blockDim.x) {
        float s = 0.f;
#pragma unroll
        for (int k = 0; k < MAX_NB; k++) s += __ldg(&ptrs[k][h]);
        nei[(size_t)b * HIDDEN + h] = s;
    }
}

// ---------------- atom gather + concat --------------------------------------
__global__ void gather_atoms(const int* __restrict__ agraph,
                             const float* __restrict__ fatoms,
                             const float* __restrict__ tree,
                             const float* __restrict__ gmsg,
                             float* __restrict__ ain)
{
    int a = blockIdx.x;
    __shared__ const float* ptrs[MAX_NB];
    int t = threadIdx.x;
    if (t < MAX_NB) {
        int j = agraph[(size_t)a * MAX_NB + t];
        ptrs[t] = (j < N_MESS) ? (tree + (size_t)j * HIDDEN)
                               : (gmsg + (size_t)(j - N_MESS) * HIDDEN);
    }
    __syncthreads();
    float* dst = ain + (size_t)a * AIN;
    for (int h = t; h < ATOM_FDIM; h += blockDim.x)
        dst[h] = fatoms[(size_t)a * ATOM_FDIM + h];
    for (int h = t; h < HIDDEN; h += blockDim.x) {
        float s = 0.f;
#pragma unroll
        for (int k = 0; k < MAX_NB; k++) s += __ldg(&ptrs[k][h]);
        dst[ATOM_FDIM + h] = s;
    }
}

// ---------------- segment mean ----------------------------------------------
__global__ void zero_out(float* __restrict__ out, float* __restrict__ cnt)
{
    int i = blockIdx.x * blockDim.x + threadIdx.x;
    if (i < N_MOLS * HIDDEN) out[i] = 0.f;
    if (i < N_MOLS) cnt[i] = 0.f;
}

__global__ void count_mols(const int* __restrict__ mol_ids, float* __restrict__ cnt)
{
    int a = blockIdx.x * blockDim.x + threadIdx.x;
    if (a < N_ATOMS) atomicAdd(&cnt[mol_ids[a]], 1.f);
}

__global__ void accum_mols(const float* __restrict__ hid,
                           const int* __restrict__ mol_ids,
                           float* __restrict__ out)
{
    int a = blockIdx.x;
    int m = mol_ids[a];
    for (int h = threadIdx.x; h < HIDDEN; h += blockDim.x)
        atomicAdd(&out[(size_t)m * HIDDEN + h], hid[(size_t)a * HIDDEN + h]);
}

__global__ void divide_mols(float* __restrict__ out, const float* __restrict__ cnt)
{
    int m = blockIdx.x;
    float inv = 1.f / cnt[m];
    for (int h = threadIdx.x; h < HIDDEN; h += blockDim.x)
        out[(size_t)m * HIDDEN + h] *= inv;
}

// ---------------- launch ------------------------------------------------------
extern "C" void kernel_launch(void* const* d_in, const int* in_sizes, int n_in,
                              void* d_out, int out_size)
{
    const float *fatoms = 0, *fbonds = 0, *tree = 0, *W_i = 0, *W_h = 0, *W_o = 0, *b_o = 0;
    const int *agraph = 0, *bgraph = 0, *mol_ids = 0;
    for (int i = 0; i < n_in; i++) {
        switch (in_sizes[i]) {
            case N_ATOMS * ATOM_FDIM: fatoms  = (const float*)d_in[i]; break;
            case N_BONDS * BOND_IN:   fbonds  = (const float*)d_in[i]; break;
            case N_ATOMS * MAX_NB:    agraph  = (const int*)  d_in[i]; break;
            case N_BONDS * MAX_NB:    bgraph  = (const int*)  d_in[i]; break;
            case N_ATOMS:             mol_ids = (const int*)  d_in[i]; break;
            case N_MESS * HIDDEN:     tree    = (const float*)d_in[i]; break;
            case HIDDEN * BOND_IN:    W_i     = (const float*)d_in[i]; break;
            case HIDDEN * HIDDEN:     W_h     = (const float*)d_in[i]; break;
            case HIDDEN * AIN:        W_o     = (const float*)d_in[i]; break;
            case HIDDEN:              b_o     = (const float*)d_in[i]; break;
            default: break;
        }
    }
    float* out = (float*)d_out;

    static float *p_binput = 0, *p_msg = 0, *p_nei = 0, *p_ain = 0, *p_hid = 0, *p_cnt = 0;
    if (!p_binput) {
        cudaGetSymbolAddress((void**)&p_binput, g_binput);
        cudaGetSymbolAddress((void**)&p_msg,    g_msg);
        cudaGetSymbolAddress((void**)&p_nei,    g_nei);
        cudaGetSymbolAddress((void**)&p_ain,    g_ain);
        cudaGetSymbolAddress((void**)&p_hid,    g_hid);
        cudaGetSymbolAddress((void**)&p_cnt,    g_cnt);
    }

    dim3 gB((HIDDEN + BN - 1) / BN, (N_BONDS + BM - 1) / BM);  // (4, 313)
    dim3 gA((HIDDEN + BN - 1) / BN, (N_ATOMS + BM - 1) / BM);  // (4, 157)

    // 1) binput = fbonds @ W_i^T ; graph_message = relu(binput)   (fused)
    gemm_nt<0><<<gB, 256>>>(fbonds, W_i, nullptr, p_binput, p_msg,
                            N_BONDS, HIDDEN, BOND_IN);

    // 2) DEPTH-1 message passing iterations
    for (int it = 0; it < DEPTH - 1; it++) {
        gather_bonds<<<N_BONDS, 256>>>(bgraph, tree, p_msg, p_nei);
        gemm_nt<1><<<gB, 256>>>(p_nei, W_h, p_binput, p_msg, nullptr,
                                N_BONDS, HIDDEN, HIDDEN);
    }

    // 3) atom-side gather + concat with fatoms
    gather_atoms<<<N_ATOMS, 256>>>(agraph, fatoms, tree, p_msg, p_ain);

    // 4) atom_hiddens = relu(ainput @ W_o^T + b_o)
    gemm_nt<2><<<gA, 256>>>(p_ain, W_o, b_o, p_hid, nullptr,
                            N_ATOMS, HIDDEN, AIN);

    // 5) segment mean over molecules
    zero_out<<<(N_MOLS * HIDDEN + 255) / 256, 256>>>(out, p_cnt);
    count_mols<<<(N_ATOMS + 255) / 256, 256>>>(mol_ids, p_cnt);
    accum_mols<<<N_ATOMS, 128>>>(p_hid, mol_ids, out);
    divide_mols<<<N_MOLS, 128>>>(out, p_cnt);
}

// round 6
// speedup vs baseline: 1.6445x; 1.4555x over previous
#include <cuda_runtime.h>
#include <cuda_bf16.h>
#include <cstdint>

#define HIDDEN    450
#define DEPTH     6
#define ATOM_FDIM 35
#define BOND_FDIM 5
#define MAX_NB    15
#define N_ATOMS   20000
#define N_BONDS   40000
#define N_MESS    16000
#define N_MOLS    1000
#define BOND_IN   (ATOM_FDIM + BOND_FDIM)   // 40
#define AIN       (ATOM_FDIM + HIDDEN)      // 485

// split-bf16 GEMM geometry: A'=[Ah|Al|Ah], B'=[Bh|Bh|Bl] over K'=3*450 -> 1408
#define KP     1408
#define KCH    64
#define NCHUNK (KP / KCH)        // 22
#define WROWS  512               // padded B' rows (>=450, multiple of 256 tile)

// ---------------- scratch (device globals; no runtime allocation) ----------
__device__ float          g_binput[(size_t)N_BONDS * HIDDEN];
__device__ float          g_msg   [(size_t)N_BONDS * HIDDEN];
__device__ __nv_bfloat16  g_neiB  [(size_t)N_BONDS * KP];     // split A'
__device__ __nv_bfloat16  g_WB    [(size_t)WROWS * KP];       // split B' (W_h)
__device__ float          g_ain   [(size_t)N_ATOMS * AIN];
__device__ float          g_hid   [(size_t)N_ATOMS * HIDDEN];
__device__ float          g_cnt   [N_MOLS];

// ---------------- PTX helpers (baseline sm_103-legal only) ------------------
__device__ __forceinline__ uint32_t smem_u32(const void* p) {
    uint32_t a;
    asm("{ .reg .u64 t; cvta.to.shared.u64 t, %1; cvt.u32.u64 %0, t; }"
        : "=r"(a) : "l"(p));
    return a;
}
#define SWZ128(off) ((off) ^ (((off) >> 3) & 0x70))
#define CP_ASYNC16(dst, src) \
    asm volatile("cp.async.cg.shared.global [%0], [%1], 16;" :: "r"(dst), "l"(src))
#define CP_COMMIT() asm volatile("cp.async.commit_group;" ::: "memory")
#define CP_WAIT(n)  asm volatile("cp.async.wait_group %0;" :: "n"(n) : "memory")

__device__ __forceinline__ void ldsm_x4(uint32_t& r0, uint32_t& r1,
                                        uint32_t& r2, uint32_t& r3, uint32_t a) {
    asm volatile("ldmatrix.sync.aligned.m8n8.x4.shared.b16 {%0,%1,%2,%3}, [%4];"
                 : "=r"(r0), "=r"(r1), "=r"(r2), "=r"(r3) : "r"(a));
}
__device__ __forceinline__ void mma_bf16(float* d, const uint32_t* a,
                                         uint32_t b0, uint32_t b1) {
    asm volatile("mma.sync.aligned.m16n8k16.row.col.f32.bf16.bf16.f32 "
                 "{%0,%1,%2,%3}, {%4,%5,%6,%7}, {%8,%9}, {%0,%1,%2,%3};"
                 : "+f"(d[0]), "+f"(d[1]), "+f"(d[2]), "+f"(d[3])
                 : "r"(a[0]), "r"(a[1]), "r"(a[2]), "r"(a[3]), "r"(b0), "r"(b1));
}

// ---------------- HMMA split-bf16 GEMM: C = relu(A'B'^T + add) --------------
// CTA tile 128m x 256n, 512 threads (16 warps of 32m x 64n), K chunks of 64,
// cp.async double-buffered. B' rows [n0, n0+256) always valid (WROWS=512).
#define CHUNK_A_BYTES (128 * KCH * 2)               // 16 KB
#define CHUNK_B_BYTES (256 * KCH * 2)               // 32 KB
#define STAGE_BYTES   (CHUNK_A_BYTES + CHUNK_B_BYTES)
#define SMEM_GEMM     (2 * STAGE_BYTES)             // 96 KB

__global__ __launch_bounds__(512, 1)
void gemm_hmma_relu(const __nv_bfloat16* __restrict__ A,
                    const __nv_bfloat16* __restrict__ B,
                    const float* __restrict__ add,   // [M, HIDDEN]
                    float* __restrict__ C, int M)
{
    extern __shared__ char smem[];
    const uint32_t sb = smem_u32(smem);
    const int tid  = threadIdx.x;
    const int lane = tid & 31, warp = tid >> 5;
    const int wm = warp & 3, wn = warp >> 2;          // 4 x 4 warps
    const int bm = blockIdx.y * 128, n0 = blockIdx.x * 256;

    // ---- async stage of chunk c into buffer b ----
    auto issue = [&](int c, int b) {
        uint32_t abase = sb + b * STAGE_BYTES;
        uint32_t bbase = abase + CHUNK_A_BYTES;
#pragma unroll
        for (int i = 0; i < 2; i++) {                 // A: 1024 float4
            int idx = tid + i * 512;
            int r = idx >> 3, q = idx & 7;
            int m = bm + r;
            uint32_t dst = abase + SWZ128((uint32_t)(r * 128 + q * 16));
            if (m < M) {
                CP_ASYNC16(dst, A + (size_t)m * KP + c * KCH + q * 8);
            } else {
                float4 z = make_float4(0.f, 0.f, 0.f, 0.f);
                *(float4*)(smem + (dst - sb)) = z;
            }
        }
#pragma unroll
        for (int i = 0; i < 4; i++) {                 // B: 2048 float4
            int idx = tid + i * 512;
            int r = idx >> 3, q = idx & 7;
            uint32_t dst = bbase + SWZ128((uint32_t)(r * 128 + q * 16));
            CP_ASYNC16(dst, B + (size_t)(n0 + r) * KP + c * KCH + q * 8);
        }
        CP_COMMIT();
    };

    float acc[2][8][4];
#pragma unroll
    for (int f = 0; f < 2; f++)
#pragma unroll
        for (int j = 0; j < 8; j++)
#pragma unroll
            for (int q = 0; q < 4; q++) acc[f][j][q] = 0.f;

    issue(0, 0);

    for (int c = 0; c < NCHUNK; c++) {
        const int b = c & 1;
        if (c + 1 < NCHUNK) { issue(c + 1, b ^ 1); CP_WAIT(1); }
        else                { CP_WAIT(0); }
        __syncthreads();

        const uint32_t abase = sb + b * STAGE_BYTES;
        const uint32_t bbase = abase + CHUNK_A_BYTES;
#pragma unroll
        for (int s = 0; s < 4; s++) {                 // 4 k16 steps per chunk
            uint32_t af[2][4];
#pragma unroll
            for (int f = 0; f < 2; f++) {
                int row = wm * 32 + f * 16 + (lane & 7) + (((lane >> 3) & 1) << 3);
                int kb  = s * 32 + (((lane >> 4) & 1) << 4);
                ldsm_x4(af[f][0], af[f][1], af[f][2], af[f][3],
                        abase + SWZ128((uint32_t)(row * 128 + kb)));
            }
            uint32_t bf[8][2];
#pragma unroll
            for (int jj = 0; jj < 4; jj++) {          // 2 n8 groups per ldmatrix
                int row = wn * 64 + jj * 16 + (lane & 7) + (((lane >> 4) & 1) << 3);
                int kb  = s * 32 + (((lane >> 3) & 1) << 4);
                uint32_t r0, r1, r2, r3;
                ldsm_x4(r0, r1, r2, r3, bbase + SWZ128((uint32_t)(row * 128 + kb)));
                bf[jj * 2][0] = r0;     bf[jj * 2][1] = r1;
                bf[jj * 2 + 1][0] = r2; bf[jj * 2 + 1][1] = r3;
            }
#pragma unroll
            for (int f = 0; f < 2; f++)
#pragma unroll
                for (int j = 0; j < 8; j++)
                    mma_bf16(acc[f][j], af[f], bf[j][0], bf[j][1]);
        }
        __syncthreads();
    }

    // ---- epilogue: add + relu + store (float2 per pair) ----
#pragma unroll
    for (int f = 0; f < 2; f++) {
        int mrow = bm + wm * 32 + f * 16 + (lane >> 2);
#pragma unroll
        for (int half = 0; half < 2; half++) {
            int m = mrow + half * 8;
            if (m >= M) continue;
#pragma unroll
            for (int j = 0; j < 8; j++) {
                int n = n0 + wn * 64 + j * 8 + (lane & 3) * 2;
                if (n >= HIDDEN) continue;
                float2 ad = *(const float2*)(add + (size_t)m * HIDDEN + n);
                float2 o;
                o.x = fmaxf(acc[f][j][half * 2 + 0] + ad.x, 0.f);
                o.y = fmaxf(acc[f][j][half * 2 + 1] + ad.y, 0.f);
                *(float2*)(C + (size_t)m * HIDDEN + n) = o;
            }
        }
    }
}

// ---------------- W_h -> split-bf16 B' ([Bh|Bh|Bl], rows>=450 zero) ---------
__global__ void convert_W(const float* __restrict__ W, __nv_bfloat16* __restrict__ WB)
{
    int idx = blockIdx.x * blockDim.x + threadIdx.x;
    if (idx >= WROWS * KP) return;
    int n = idx / KP, k = idx % KP;
    __nv_bfloat16 out = __float2bfloat16(0.f);
    if (n < HIDDEN) {
        if (k < HIDDEN) out = __float2bfloat16(W[(size_t)n * HIDDEN + k]);
        else if (k < 2 * HIDDEN) out = __float2bfloat16(W[(size_t)n * HIDDEN + (k - HIDDEN)]);
        else if (k < 3 * HIDDEN) {
            float w = W[(size_t)n * HIDDEN + (k - 2 * HIDDEN)];
            float hi = __bfloat162float(__float2bfloat16(w));
            out = __float2bfloat16(w - hi);
        }
    }
    WB[idx] = out;
}

// ---------------- gather-sum -> split-bf16 A' ([Ah|Al|Ah]) ------------------
__global__ void gather_bonds(const int* __restrict__ bgraph,
                             const float* __restrict__ tree,
                             const float* __restrict__ gmsg,
                             __nv_bfloat16* __restrict__ neiB)
{
    int b = blockIdx.x;
    __shared__ const float* ptrs[MAX_NB];
    int t = threadIdx.x;
    if (t < MAX_NB) {
        int j = bgraph[(size_t)b * MAX_NB + t];
        ptrs[t] = (j < N_MESS) ? (tree + (size_t)j * HIDDEN)
                               : (gmsg + (size_t)(j - N_MESS) * HIDDEN);
    }
    __syncthreads();
    __nv_bfloat16* row = neiB + (size_t)b * KP;
    for (int h2 = t; h2 < HIDDEN / 2; h2 += blockDim.x) {
        float2 s = make_float2(0.f, 0.f);
#pragma unroll
        for (int k = 0; k < MAX_NB; k++) {
            float2 v = *(const float2*)(ptrs[k] + 2 * h2);
            s.x += v.x; s.y += v.y;
        }
        __nv_bfloat16 h0 = __float2bfloat16(s.x), h1 = __float2bfloat16(s.y);
        __nv_bfloat16 l0 = __float2bfloat16(s.x - __bfloat162float(h0));
        __nv_bfloat16 l1 = __float2bfloat16(s.y - __bfloat162float(h1));
        __nv_bfloat162 hi; hi.x = h0; hi.y = h1;
        __nv_bfloat162 lo; lo.x = l0; lo.y = l1;
        *(__nv_bfloat162*)(row + 2 * h2)              = hi;   // Ah
        *(__nv_bfloat162*)(row + HIDDEN + 2 * h2)     = lo;   // Al
        *(__nv_bfloat162*)(row + 2 * HIDDEN + 2 * h2) = hi;   // Ah
    }
    for (int k = 3 * HIDDEN + t; k < KP; k += blockDim.x)
        row[k] = __float2bfloat16(0.f);
}

// ---------------- fp32 SIMT GEMM (gemm0 / gemm2) ----------------------------
#define BM 128
#define BN 128
#define BK 16
#define SPITCH 132

template <int MODE>  // 0: C=acc, C2=relu(acc) ; 2: C=relu(acc+add[n])
__global__ __launch_bounds__(256, 2)
void gemm_nt(const float* __restrict__ A, const float* __restrict__ W,
             const float* __restrict__ add, float* __restrict__ C,
             float* __restrict__ C2, int M, int N, int K)
{
    __shared__ float sA[2][BK * SPITCH];
    __shared__ float sB[2][BK * SPITCH];
    const int bm = blockIdx.y * BM, bn = blockIdx.x * BN;
    const int tid = threadIdx.x, tx = tid & 15, ty = tid >> 4;

    float acc[8][8];
#pragma unroll
    for (int i = 0; i < 8; i++)
#pragma unroll
        for (int j = 0; j < 8; j++) acc[i][j] = 0.f;

    const int ntiles = (K + BK - 1) / BK;
    float ar[8], br[8];
#pragma unroll
    for (int i = 0; i < 8; i++) {
        int idx = tid + i * 256, r = idx >> 4, kk = idx & 15;
        int m = bm + r;
        ar[i] = (m < M && kk < K) ? A[(size_t)m * K + kk] : 0.f;
        int n = bn + r;
        br[i] = (n < N && kk < K) ? W[(size_t)n * K + kk] : 0.f;
    }
#pragma unroll
    for (int i = 0; i < 8; i++) {
        int idx = tid + i * 256, r = idx >> 4, kk = idx & 15;
        sA[0][kk * SPITCH + r] = ar[i];
        sB[0][kk * SPITCH + r] = br[i];
    }
    __syncthreads();

    int buf = 0;
    for (int t = 0; t < ntiles; t++) {
        if (t + 1 < ntiles) {
            int k0 = (t + 1) * BK;
#pragma unroll
            for (int i = 0; i < 8; i++) {
                int idx = tid + i * 256, r = idx >> 4, kk = idx & 15;
                int m = bm + r, k = k0 + kk;
                ar[i] = (m < M && k < K) ? A[(size_t)m * K + k] : 0.f;
                int n = bn + r;
                br[i] = (n < N && k < K) ? W[(size_t)n * K + k] : 0.f;
            }
        }
        const float* pa = sA[buf];
        const float* pb = sB[buf];
#pragma unroll
        for (int kk = 0; kk < BK; kk++) {
            float a_[8], b_[8];
            *(float4*)&a_[0] = *(const float4*)&pa[kk * SPITCH + ty * 8];
            *(float4*)&a_[4] = *(const float4*)&pa[kk * SPITCH + ty * 8 + 4];
            *(float4*)&b_[0] = *(const float4*)&pb[kk * SPITCH + tx * 8];
            *(float4*)&b_[4] = *(const float4*)&pb[kk * SPITCH + tx * 8 + 4];
#pragma unroll
            for (int i = 0; i < 8; i++)
#pragma unroll
                for (int j = 0; j < 8; j++) acc[i][j] += a_[i] * b_[j];
        }
        if (t + 1 < ntiles) {
            int nb = buf ^ 1;
#pragma unroll
            for (int i = 0; i < 8; i++) {
                int idx = tid + i * 256, r = idx >> 4, kk = idx & 15;
                sA[nb][kk * SPITCH + r] = ar[i];
                sB[nb][kk * SPITCH + r] = br[i];
            }
            __syncthreads();
            buf = nb;
        }
    }
#pragma unroll
    for (int i = 0; i < 8; i++) {
        int m = bm + ty * 8 + i;
        if (m >= M) break;
#pragma unroll
        for (int j = 0; j < 8; j++) {
            int n = bn + tx * 8 + j;
            if (n < N) {
                float v = acc[i][j];
                if (MODE == 0) {
                    C [(size_t)m * N + n] = v;
                    C2[(size_t)m * N + n] = fmaxf(v, 0.f);
                } else {
                    C[(size_t)m * N + n] = fmaxf(v + add[n], 0.f);
                }
            }
        }
    }
}

// ---------------- atom gather + concat --------------------------------------
__global__ void gather_atoms(const int* __restrict__ agraph,
                             const float* __restrict__ fatoms,
                             const float* __restrict__ tree,
                             const float* __restrict__ gmsg,
                             float* __restrict__ ain)
{
    int a = blockIdx.x;
    __shared__ const float* ptrs[MAX_NB];
    int t = threadIdx.x;
    if (t < MAX_NB) {
        int j = agraph[(size_t)a * MAX_NB + t];
        ptrs[t] = (j < N_MESS) ? (tree + (size_t)j * HIDDEN)
                               : (gmsg + (size_t)(j - N_MESS) * HIDDEN);
    }
    __syncthreads();
    float* dst = ain + (size_t)a * AIN;
    for (int h = t; h < ATOM_FDIM; h += blockDim.x)
        dst[h] = fatoms[(size_t)a * ATOM_FDIM + h];
    for (int h2 = t; h2 < HIDDEN / 2; h2 += blockDim.x) {
        float2 s = make_float2(0.f, 0.f);
#pragma unroll
        for (int k = 0; k < MAX_NB; k++) {
            float2 v = *(const float2*)(ptrs[k] + 2 * h2);
            s.x += v.x; s.y += v.y;
        }
        dst[ATOM_FDIM + 2 * h2]     = s.x;
        dst[ATOM_FDIM + 2 * h2 + 1] = s.y;
    }
}

// ---------------- segment mean ----------------------------------------------
__global__ void zero_out(float* __restrict__ out, float* __restrict__ cnt)
{
    int i = blockIdx.x * blockDim.x + threadIdx.x;
    if (i < N_MOLS * HIDDEN) out[i] = 0.f;
    if (i < N_MOLS) cnt[i] = 0.f;
}
__global__ void count_mols(const int* __restrict__ mol_ids, float* __restrict__ cnt)
{
    int a = blockIdx.x * blockDim.x + threadIdx.x;
    if (a < N_ATOMS) atomicAdd(&cnt[mol_ids[a]], 1.f);
}
__global__ void accum_mols(const float* __restrict__ hid,
                           const int* __restrict__ mol_ids,
                           float* __restrict__ out)
{
    int a = blockIdx.x;
    int m = mol_ids[a];
    for (int h = threadIdx.x; h < HIDDEN; h += blockDim.x)
        atomicAdd(&out[(size_t)m * HIDDEN + h], hid[(size_t)a * HIDDEN + h]);
}
__global__ void divide_mols(float* __restrict__ out, const float* __restrict__ cnt)
{
    int m = blockIdx.x;
    float inv = 1.f / cnt[m];
    for (int h = threadIdx.x; h < HIDDEN; h += blockDim.x)
        out[(size_t)m * HIDDEN + h] *= inv;
}

// ---------------- launch ------------------------------------------------------
extern "C" void kernel_launch(void* const* d_in, const int* in_sizes, int n_in,
                              void* d_out, int out_size)
{
    const float *fatoms = 0, *fbonds = 0, *tree = 0, *W_i = 0, *W_h = 0, *W_o = 0, *b_o = 0;
    const int *agraph = 0, *bgraph = 0, *mol_ids = 0;
    for (int i = 0; i < n_in; i++) {
        switch (in_sizes[i]) {
            case N_ATOMS * ATOM_FDIM: fatoms  = (const float*)d_in[i]; break;
            case N_BONDS * BOND_IN:   fbonds  = (const float*)d_in[i]; break;
            case N_ATOMS * MAX_NB:    agraph  = (const int*)  d_in[i]; break;
            case N_BONDS * MAX_NB:    bgraph  = (const int*)  d_in[i]; break;
            case N_ATOMS:             mol_ids = (const int*)  d_in[i]; break;
            case N_MESS * HIDDEN:     tree    = (const float*)d_in[i]; break;
            case HIDDEN * BOND_IN:    W_i     = (const float*)d_in[i]; break;
            case HIDDEN * HIDDEN:     W_h     = (const float*)d_in[i]; break;
            case HIDDEN * AIN:        W_o     = (const float*)d_in[i]; break;
            case HIDDEN:              b_o     = (const float*)d_in[i]; break;
            default: break;
        }
    }
    float* out = (float*)d_out;

    static float *p_binput = 0, *p_msg = 0, *p_ain = 0, *p_hid = 0, *p_cnt = 0;
    static __nv_bfloat16 *p_neiB = 0, *p_WB = 0;
    if (!p_binput) {
        cudaGetSymbolAddress((void**)&p_binput, g_binput);
        cudaGetSymbolAddress((void**)&p_msg,    g_msg);
        cudaGetSymbolAddress((void**)&p_neiB,   g_neiB);
        cudaGetSymbolAddress((void**)&p_WB,     g_WB);
        cudaGetSymbolAddress((void**)&p_ain,    g_ain);
        cudaGetSymbolAddress((void**)&p_hid,    g_hid);
        cudaGetSymbolAddress((void**)&p_cnt,    g_cnt);
        cudaFuncSetAttribute(gemm_hmma_relu,
                             cudaFuncAttributeMaxDynamicSharedMemorySize, SMEM_GEMM);
    }

    dim3 gB((HIDDEN + BN - 1) / BN, (N_BONDS + BM - 1) / BM);  // (4, 313)
    dim3 gA((HIDDEN + BN - 1) / BN, (N_ATOMS + BM - 1) / BM);  // (4, 157)
    dim3 gM(2, (N_BONDS + 127) / 128);                         // (2, 313)

    // 0) W_h -> split bf16 B'
    convert_W<<<(WROWS * KP + 255) / 256, 256>>>(W_h, p_WB);

    // 1) binput = fbonds @ W_i^T ; graph_message = relu(binput)   (fused)
    gemm_nt<0><<<gB, 256>>>(fbonds, W_i, nullptr, p_binput, p_msg,
                            N_BONDS, HIDDEN, BOND_IN);

    // 2) DEPTH-1 message passing iterations (HMMA split-bf16 GEMM)
    for (int it = 0; it < DEPTH - 1; it++) {
        gather_bonds<<<N_BONDS, 256>>>(bgraph, tree, p_msg, p_neiB);
        gemm_hmma_relu<<<gM, 512, SMEM_GEMM>>>(p_neiB, p_WB, p_binput, p_msg, N_BONDS);
    }

    // 3) atom-side gather + concat with fatoms
    gather_atoms<<<N_ATOMS, 256>>>(agraph, fatoms, tree, p_msg, p_ain);

    // 4) atom_hiddens = relu(ainput @ W_o^T + b_o)
    gemm_nt<2><<<gA, 256>>>(p_ain, W_o, b_o, p_hid, nullptr,
                            N_ATOMS, HIDDEN, AIN);

    // 5) segment mean over molecules
    zero_out<<<(N_MOLS * HIDDEN + 255) / 256, 256>>>(out, p_cnt);
    count_mols<<<(N_ATOMS + 255) / 256, 256>>>(mol_ids, p_cnt);
    accum_mols<<<N_ATOMS, 128>>>(p_hid, mol_ids, out);
    divide_mols<<<N_MOLS, 128>>>(out, p_cnt);
}

// round 8
// speedup vs baseline: 1.6991x; 1.0332x over previous
#include <cuda_runtime.h>
#include <cuda_bf16.h>
#include <cstdint>

#define HIDDEN    450
#define DEPTH     6
#define ATOM_FDIM 35
#define BOND_FDIM 5
#define MAX_NB    15
#define N_ATOMS   20000
#define N_BONDS   40000
#define N_MESS    16000
#define N_MOLS    1000
#define BOND_IN   (ATOM_FDIM + BOND_FDIM)   // 40
#define AIN       (ATOM_FDIM + HIDDEN)      // 485

// split-bf16 geometry: A'=[Ah|Al|Ah], B'=[Bh|Bh|Bl]
#define KP     1408              // pad(3*450) in 64s, 22 chunks
#define KP2    1472              // pad(3*485) in 64s, 23 chunks
#define KCH    64
#define WROWS  512               // padded B' rows

// ---------------- scratch (device globals; no runtime allocation) ----------
__device__ float          g_binput[(size_t)N_BONDS * HIDDEN];
__device__ float          g_msg   [(size_t)N_BONDS * HIDDEN];
__device__ __nv_bfloat16  g_neiB  [(size_t)N_BONDS * KP];     // split A' (bonds)
__device__ __nv_bfloat16  g_WB    [(size_t)WROWS * KP];       // split B' (W_h)
__device__ __nv_bfloat16  g_ainB  [(size_t)N_ATOMS * KP2];    // split A' (atoms)
__device__ __nv_bfloat16  g_WoB   [(size_t)WROWS * KP2];      // split B' (W_o)
__device__ float          g_hid   [(size_t)N_ATOMS * HIDDEN];
__device__ float          g_cnt   [N_MOLS];

// ---------------- PTX helpers (baseline sm_103-legal only) ------------------
__device__ __forceinline__ uint32_t smem_u32(const void* p) {
    uint32_t a;
    asm("{ .reg .u64 t; cvta.to.shared.u64 t, %1; cvt.u32.u64 %0, t; }"
        : "=r"(a) : "l"(p));
    return a;
}
#define SWZ128(off) ((off) ^ (((off) >> 3) & 0x70))
#define CP_ASYNC16(dst, src) \
    asm volatile("cp.async.cg.shared.global [%0], [%1], 16;" :: "r"(dst), "l"(src))
#define CP_COMMIT() asm volatile("cp.async.commit_group;" ::: "memory")
#define CP_WAIT(n)  asm volatile("cp.async.wait_group %0;" :: "n"(n) : "memory")

__device__ __forceinline__ void ldsm_x4(uint32_t& r0, uint32_t& r1,
                                        uint32_t& r2, uint32_t& r3, uint32_t a) {
    asm volatile("ldmatrix.sync.aligned.m8n8.x4.shared.b16 {%0,%1,%2,%3}, [%4];"
                 : "=r"(r0), "=r"(r1), "=r"(r2), "=r"(r3) : "r"(a));
}
__device__ __forceinline__ void mma_bf16(float* d, const uint32_t* a,
                                         uint32_t b0, uint32_t b1) {
    asm volatile("mma.sync.aligned.m16n8k16.row.col.f32.bf16.bf16.f32 "
                 "{%0,%1,%2,%3}, {%4,%5,%6,%7}, {%8,%9}, {%0,%1,%2,%3};"
                 : "+f"(d[0]), "+f"(d[1]), "+f"(d[2]), "+f"(d[3])
                 : "r"(a[0]), "r"(a[1]), "r"(a[2]), "r"(a[3]), "r"(b0), "r"(b1));
}

// ---------------- HMMA split-bf16 GEMM: C = relu(A'B'^T + add) --------------
// CTA tile 128m x 256n, 512 threads (4x4 warps of 32m x 64n), K chunks of 64,
// cp.async double-buffered. ADDMODE 1: add[m*HIDDEN+n]; 2: add[n] (bias).
#define CHUNK_A_BYTES (128 * KCH * 2)               // 16 KB
#define CHUNK_B_BYTES (256 * KCH * 2)               // 32 KB
#define STAGE_BYTES   (CHUNK_A_BYTES + CHUNK_B_BYTES)
#define SMEM_GEMM     (2 * STAGE_BYTES)             // 96 KB

template <int KPAD, int ADDMODE>
__global__ __launch_bounds__(512, 1)
void gemm_hmma_relu(const __nv_bfloat16* __restrict__ A,
                    const __nv_bfloat16* __restrict__ B,
                    const float* __restrict__ add,
                    float* __restrict__ C, int M)
{
    constexpr int NCH = KPAD / KCH;
    extern __shared__ char smem[];
    const uint32_t sb = smem_u32(smem);
    const int tid  = threadIdx.x;
    const int lane = tid & 31, warp = tid >> 5;
    const int wm = warp & 3, wn = warp >> 2;
    const int bm = blockIdx.y * 128, n0 = blockIdx.x * 256;

    auto issue = [&](int c, int b) {
        uint32_t abase = sb + b * STAGE_BYTES;
        uint32_t bbase = abase + CHUNK_A_BYTES;
#pragma unroll
        for (int i = 0; i < 2; i++) {                 // A: 1024 float4
            int idx = tid + i * 512;
            int r = idx >> 3, q = idx & 7;
            int m = bm + r;
            uint32_t dst = abase + SWZ128((uint32_t)(r * 128 + q * 16));
            if (m < M) {
                CP_ASYNC16(dst, A + (size_t)m * KPAD + c * KCH + q * 8);
            } else {
                float4 z = make_float4(0.f, 0.f, 0.f, 0.f);
                *(float4*)(smem + (dst - sb)) = z;
            }
        }
#pragma unroll
        for (int i = 0; i < 4; i++) {                 // B: 2048 float4
            int idx = tid + i * 512;
            int r = idx >> 3, q = idx & 7;
            uint32_t dst = bbase + SWZ128((uint32_t)(r * 128 + q * 16));
            CP_ASYNC16(dst, B + (size_t)(n0 + r) * KPAD + c * KCH + q * 8);
        }
        CP_COMMIT();
    };

    float acc[2][8][4];
#pragma unroll
    for (int f = 0; f < 2; f++)
#pragma unroll
        for (int j = 0; j < 8; j++)
#pragma unroll
            for (int q = 0; q < 4; q++) acc[f][j][q] = 0.f;

    issue(0, 0);

    for (int c = 0; c < NCH; c++) {
        const int b = c & 1;
        if (c + 1 < NCH) { issue(c + 1, b ^ 1); CP_WAIT(1); }
        else             { CP_WAIT(0); }
        __syncthreads();

        const uint32_t abase = sb + b * STAGE_BYTES;
        const uint32_t bbase = abase + CHUNK_A_BYTES;
#pragma unroll
        for (int s = 0; s < 4; s++) {
            uint32_t af[2][4];
#pragma unroll
            for (int f = 0; f < 2; f++) {
                int row = wm * 32 + f * 16 + (lane & 7) + (((lane >> 3) & 1) << 3);
                int kb  = s * 32 + (((lane >> 4) & 1) << 4);
                ldsm_x4(af[f][0], af[f][1], af[f][2], af[f][3],
                        abase + SWZ128((uint32_t)(row * 128 + kb)));
            }
            uint32_t bf[8][2];
#pragma unroll
            for (int jj = 0; jj < 4; jj++) {
                int row = wn * 64 + jj * 16 + (lane & 7) + (((lane >> 4) & 1) << 3);
                int kb  = s * 32 + (((lane >> 3) & 1) << 4);
                uint32_t r0, r1, r2, r3;
                ldsm_x4(r0, r1, r2, r3, bbase + SWZ128((uint32_t)(row * 128 + kb)));
                bf[jj * 2][0] = r0;     bf[jj * 2][1] = r1;
                bf[jj * 2 + 1][0] = r2; bf[jj * 2 + 1][1] = r3;
            }
#pragma unroll
            for (int f = 0; f < 2; f++)
#pragma unroll
                for (int j = 0; j < 8; j++)
                    mma_bf16(acc[f][j], af[f], bf[j][0], bf[j][1]);
        }
        __syncthreads();
    }

#pragma unroll
    for (int f = 0; f < 2; f++) {
        int mrow = bm + wm * 32 + f * 16 + (lane >> 2);
#pragma unroll
        for (int half = 0; half < 2; half++) {
            int m = mrow + half * 8;
            if (m >= M) continue;
#pragma unroll
            for (int j = 0; j < 8; j++) {
                int n = n0 + wn * 64 + j * 8 + (lane & 3) * 2;
                if (n >= HIDDEN) continue;
                float2 ad;
                if (ADDMODE == 1) ad = *(const float2*)(add + (size_t)m * HIDDEN + n);
                else              ad = *(const float2*)(add + n);
                float2 o;
                o.x = fmaxf(acc[f][j][half * 2 + 0] + ad.x, 0.f);
                o.y = fmaxf(acc[f][j][half * 2 + 1] + ad.y, 0.f);
                *(float2*)(C + (size_t)m * HIDDEN + n) = o;
            }
        }
    }
}

// ---------------- W (fp32 [HIDDEN, K]) -> split-bf16 B' [Bh|Bh|Bl] ----------
template <int K, int KPAD>
__global__ void convert_W(const float* __restrict__ W, __nv_bfloat16* __restrict__ WB)
{
    int idx = blockIdx.x * blockDim.x + threadIdx.x;
    if (idx >= WROWS * KPAD) return;
    int n = idx / KPAD, k = idx % KPAD;
    __nv_bfloat16 out = __float2bfloat16(0.f);
    if (n < HIDDEN) {
        if (k < K) out = __float2bfloat16(W[(size_t)n * K + k]);
        else if (k < 2 * K) out = __float2bfloat16(W[(size_t)n * K + (k - K)]);
        else if (k < 3 * K) {
            float w = W[(size_t)n * K + (k - 2 * K)];
            float hi = __bfloat162float(__float2bfloat16(w));
            out = __float2bfloat16(w - hi);
        }
    }
    WB[idx] = out;
}

// ---------------- gather-sum -> split-bf16 A' ([Ah|Al|Ah]) ------------------
__global__ void gather_bonds(const int* __restrict__ bgraph,
                             const float* __restrict__ tree,
                             const float* __restrict__ gmsg,
                             __nv_bfloat16* __restrict__ neiB)
{
    int b = blockIdx.x;
    __shared__ const float* ptrs[MAX_NB];
    int t = threadIdx.x;
    if (t < MAX_NB) {
        int j = bgraph[(size_t)b * MAX_NB + t];
        ptrs[t] = (j < N_MESS) ? (tree + (size_t)j * HIDDEN)
                               : (gmsg + (size_t)(j - N_MESS) * HIDDEN);
    }
    __syncthreads();
    __nv_bfloat16* row = neiB + (size_t)b * KP;
    for (int h2 = t; h2 < HIDDEN / 2; h2 += blockDim.x) {
        float2 s = make_float2(0.f, 0.f);
#pragma unroll
        for (int k = 0; k < MAX_NB; k++) {
            float2 v = *(const float2*)(ptrs[k] + 2 * h2);
            s.x += v.x; s.y += v.y;
        }
        __nv_bfloat16 h0 = __float2bfloat16(s.x), h1 = __float2bfloat16(s.y);
        __nv_bfloat16 l0 = __float2bfloat16(s.x - __bfloat162float(h0));
        __nv_bfloat16 l1 = __float2bfloat16(s.y - __bfloat162float(h1));
        __nv_bfloat162 hi; hi.x = h0; hi.y = h1;
        __nv_bfloat162 lo; lo.x = l0; lo.y = l1;
        *(__nv_bfloat162*)(row + 2 * h2)              = hi;   // Ah
        *(__nv_bfloat162*)(row + HIDDEN + 2 * h2)     = lo;   // Al
        *(__nv_bfloat162*)(row + 2 * HIDDEN + 2 * h2) = hi;   // Ah
    }
    for (int k = 3 * HIDDEN + t; k < KP; k += blockDim.x)
        row[k] = __float2bfloat16(0.f);
}

// ---------------- atom gather + concat -> split-bf16 A'2 --------------------
__global__ void gather_atoms(const int* __restrict__ agraph,
                             const float* __restrict__ fatoms,
                             const float* __restrict__ tree,
                             const float* __restrict__ gmsg,
                             __nv_bfloat16* __restrict__ ainB)
{
    int a = blockIdx.x;
    __shared__ const float* ptrs[MAX_NB];
    int t = threadIdx.x;
    if (t < MAX_NB) {
        int j = agraph[(size_t)a * MAX_NB + t];
        ptrs[t] = (j < N_MESS) ? (tree + (size_t)j * HIDDEN)
                               : (gmsg + (size_t)(j - N_MESS) * HIDDEN);
    }
    __syncthreads();
    __nv_bfloat16* row = ainB + (size_t)a * KP2;
    // fatoms part (h = 0..34)
    for (int h = t; h < ATOM_FDIM; h += blockDim.x) {
        float v = fatoms[(size_t)a * ATOM_FDIM + h];
        __nv_bfloat16 hi = __float2bfloat16(v);
        __nv_bfloat16 lo = __float2bfloat16(v - __bfloat162float(hi));
        row[h] = hi; row[AIN + h] = lo; row[2 * AIN + h] = hi;
    }
    // gathered part (h = 35 + 2*h2 .. ) — float2 loads, scalar bf16 stores
    for (int h2 = t; h2 < HIDDEN / 2; h2 += blockDim.x) {
        float2 s = make_float2(0.f, 0.f);
#pragma unroll
        for (int k = 0; k < MAX_NB; k++) {
            float2 v = *(const float2*)(ptrs[k] + 2 * h2);
            s.x += v.x; s.y += v.y;
        }
        int h = ATOM_FDIM + 2 * h2;
        __nv_bfloat16 h0 = __float2bfloat16(s.x), h1 = __float2bfloat16(s.y);
        __nv_bfloat16 l0 = __float2bfloat16(s.x - __bfloat162float(h0));
        __nv_bfloat16 l1 = __float2bfloat16(s.y - __bfloat162float(h1));
        row[h]               = h0; row[h + 1]               = h1;
        row[AIN + h]         = l0; row[AIN + h + 1]         = l1;
        row[2 * AIN + h]     = h0; row[2 * AIN + h + 1]     = h1;
    }
    for (int k = 3 * AIN + t; k < KP2; k += blockDim.x)
        row[k] = __float2bfloat16(0.f);
}

// ---------------- fp32 SIMT GEMM (gemm0 only: K=40) -------------------------
#define BM 128
#define BN 128
#define BK 16
#define SPITCH 132

__global__ __launch_bounds__(256, 2)
void gemm_nt0(const float* __restrict__ A, const float* __restrict__ W,
              float* __restrict__ C, float* __restrict__ C2,
              int M, int N, int K)
{
    __shared__ float sA[2][BK * SPITCH];
    __shared__ float sB[2][BK * SPITCH];
    const int bm = blockIdx.y * BM, bn = blockIdx.x * BN;
    const int tid = threadIdx.x, tx = tid & 15, ty = tid >> 4;

    float acc[8][8];
#pragma unroll
    for (int i = 0; i < 8; i++)
#pragma unroll
        for (int j = 0; j < 8; j++) acc[i][j] = 0.f;

    const int ntiles = (K + BK - 1) / BK;
    float ar[8], br[8];
#pragma unroll
    for (int i = 0; i < 8; i++) {
        int idx = tid + i * 256, r = idx >> 4, kk = idx & 15;
        int m = bm + r;
        ar[i] = (m < M && kk < K) ? A[(size_t)m * K + kk] : 0.f;
        int n = bn + r;
        br[i] = (n < N && kk < K) ? W[(size_t)n * K + kk] : 0.f;
    }
#pragma unroll
    for (int i = 0; i < 8; i++) {
        int idx = tid + i * 256, r = idx >> 4, kk = idx & 15;
        sA[0][kk * SPITCH + r] = ar[i];
        sB[0][kk * SPITCH + r] = br[i];
    }
    __syncthreads();

    int buf = 0;
    for (int t = 0; t < ntiles; t++) {
        if (t + 1 < ntiles) {
            int k0 = (t + 1) * BK;
#pragma unroll
            for (int i = 0; i < 8; i++) {
                int idx = tid + i * 256, r = idx >> 4, kk = idx & 15;
                int m = bm + r, k = k0 + kk;
                ar[i] = (m < M && k < K) ? A[(size_t)m * K + k] : 0.f;
                int n = bn + r;
                br[i] = (n < N && k < K) ? W[(size_t)n * K + k] : 0.f;
            }
        }
        const float* pa = sA[buf];
        const float* pb = sB[buf];
#pragma unroll
        for (int kk = 0; kk < BK; kk++) {
            float a_[8], b_[8];
            *(float4*)&a_[0] = *(const float4*)&pa[kk * SPITCH + ty * 8];
            *(float4*)&a_[4] = *(const float4*)&pa[kk * SPITCH + ty * 8 + 4];
            *(float4*)&b_[0] = *(const float4*)&pb[kk * SPITCH + tx * 8];
            *(float4*)&b_[4] = *(const float4*)&pb[kk * SPITCH + tx * 8 + 4];
#pragma unroll
            for (int i = 0; i < 8; i++)
#pragma unroll
                for (int j = 0; j < 8; j++) acc[i][j] += a_[i] * b_[j];
        }
        if (t + 1 < ntiles) {
            int nb = buf ^ 1;
#pragma unroll
            for (int i = 0; i < 8; i++) {
                int idx = tid + i * 256, r = idx >> 4, kk = idx & 15;
                sA[nb][kk * SPITCH + r] = ar[i];
                sB[nb][kk * SPITCH + r] = br[i];
            }
            __syncthreads();
            buf = nb;
        }
    }
#pragma unroll
    for (int i = 0; i < 8; i++) {
        int m = bm + ty * 8 + i;
        if (m >= M) break;
#pragma unroll
        for (int j = 0; j < 8; j++) {
            int n = bn + tx * 8 + j;
            if (n < N) {
                float v = acc[i][j];
                C [(size_t)m * N + n] = v;
                C2[(size_t)m * N + n] = fmaxf(v, 0.f);
            }
        }
    }
}

// ---------------- segment mean ----------------------------------------------
__global__ void zero_out(float* __restrict__ out, float* __restrict__ cnt)
{
    int i = blockIdx.x * blockDim.x + threadIdx.x;
    if (i < N_MOLS * HIDDEN) out[i] = 0.f;
    if (i < N_MOLS) cnt[i] = 0.f;
}
__global__ void count_mols(const int* __restrict__ mol_ids, float* __restrict__ cnt)
{
    int a = blockIdx.x * blockDim.x + threadIdx.x;
    if (a < N_ATOMS) atomicAdd(&cnt[mol_ids[a]], 1.f);
}
__global__ void accum_mols(const float* __restrict__ hid,
                           const int* __restrict__ mol_ids,
                           float* __restrict__ out)
{
    int a = blockIdx.x;
    int m = mol_ids[a];
    for (int h = threadIdx.x; h < HIDDEN; h += blockDim.x)
        atomicAdd(&out[(size_t)m * HIDDEN + h], hid[(size_t)a * HIDDEN + h]);
}
__global__ void divide_mols(float* __restrict__ out, const float* __restrict__ cnt)
{
    int m = blockIdx.x;
    float inv = 1.f / cnt[m];
    for (int h = threadIdx.x; h < HIDDEN; h += blockDim.x)
        out[(size_t)m * HIDDEN + h] *= inv;
}

// ---------------- launch ------------------------------------------------------
extern "C" void kernel_launch(void* const* d_in, const int* in_sizes, int n_in,
                              void* d_out, int out_size)
{
    const float *fatoms = 0, *fbonds = 0, *tree = 0, *W_i = 0, *W_h = 0, *W_o = 0, *b_o = 0;
    const int *agraph = 0, *bgraph = 0, *mol_ids = 0;
    for (int i = 0; i < n_in; i++) {
        switch (in_sizes[i]) {
            case N_ATOMS * ATOM_FDIM: fatoms  = (const float*)d_in[i]; break;
            case N_BONDS * BOND_IN:   fbonds  = (const float*)d_in[i]; break;
            case N_ATOMS * MAX_NB:    agraph  = (const int*)  d_in[i]; break;
            case N_BONDS * MAX_NB:    bgraph  = (const int*)  d_in[i]; break;
            case N_ATOMS:             mol_ids = (const int*)  d_in[i]; break;
            case N_MESS * HIDDEN:     tree    = (const float*)d_in[i]; break;
            case HIDDEN * BOND_IN:    W_i     = (const float*)d_in[i]; break;
            case HIDDEN * HIDDEN:     W_h     = (const float*)d_in[i]; break;
            case HIDDEN * AIN:        W_o     = (const float*)d_in[i]; break;
            case HIDDEN:              b_o     = (const float*)d_in[i]; break;
            default: break;
        }
    }
    float* out = (float*)d_out;

    static float *p_binput = 0, *p_msg = 0, *p_hid = 0, *p_cnt = 0;
    static __nv_bfloat16 *p_neiB = 0, *p_WB = 0, *p_ainB = 0, *p_WoB = 0;
    if (!p_binput) {
        cudaGetSymbolAddress((void**)&p_binput, g_binput);
        cudaGetSymbolAddress((void**)&p_msg,    g_msg);
        cudaGetSymbolAddress((void**)&p_neiB,   g_neiB);
        cudaGetSymbolAddress((void**)&p_WB,     g_WB);
        cudaGetSymbolAddress((void**)&p_ainB,   g_ainB);
        cudaGetSymbolAddress((void**)&p_WoB,    g_WoB);
        cudaGetSymbolAddress((void**)&p_hid,    g_hid);
        cudaGetSymbolAddress((void**)&p_cnt,    g_cnt);
        cudaFuncSetAttribute(gemm_hmma_relu<KP, 1>,
                             cudaFuncAttributeMaxDynamicSharedMemorySize, SMEM_GEMM);
        cudaFuncSetAttribute(gemm_hmma_relu<KP2, 2>,
                             cudaFuncAttributeMaxDynamicSharedMemorySize, SMEM_GEMM);
    }

    dim3 gB((HIDDEN + BN - 1) / BN, (N_BONDS + BM - 1) / BM);  // (4, 313)
    dim3 gM(2, (N_BONDS + 127) / 128);                         // (2, 313)
    dim3 gM2(2, (N_ATOMS + 127) / 128);                        // (2, 157)

    // 0) weight conversions
    convert_W<HIDDEN, KP ><<<(WROWS * KP  + 255) / 256, 256>>>(W_h, p_WB);
    convert_W<AIN,    KP2><<<(WROWS * KP2 + 255) / 256, 256>>>(W_o, p_WoB);

    // 1) binput = fbonds @ W_i^T ; graph_message = relu(binput)   (fused)
    gemm_nt0<<<gB, 256>>>(fbonds, W_i, p_binput, p_msg, N_BONDS, HIDDEN, BOND_IN);

    // 2) DEPTH-1 message passing iterations (HMMA split-bf16)
    for (int it = 0; it < DEPTH - 1; it++) {
        gather_bonds<<<N_BONDS, 256>>>(bgraph, tree, p_msg, p_neiB);
        gemm_hmma_relu<KP, 1><<<gM, 512, SMEM_GEMM>>>(p_neiB, p_WB, p_binput,
                                                      p_msg, N_BONDS);
    }

    // 3) atom-side gather + concat -> split-bf16 A'2
    gather_atoms<<<N_ATOMS, 256>>>(agraph, fatoms, tree, p_msg, p_ainB);

    // 4) atom_hiddens = relu(ainput @ W_o^T + b_o)   (HMMA split-bf16)
    gemm_hmma_relu<KP2, 2><<<gM2, 512, SMEM_GEMM>>>(p_ainB, p_WoB, b_o,
                                                    p_hid, N_ATOMS);

    // 5) segment mean over molecules
    zero_out<<<(N_MOLS * HIDDEN + 255) / 256, 256>>>(out, p_cnt);
    count_mols<<<(N_ATOMS + 255) / 256, 256>>>(mol_ids, p_cnt);
    accum_mols<<<N_ATOMS, 128>>>(p_hid, mol_ids, out);
    divide_mols<<<N_MOLS, 128>>>(out, p_cnt);
}

// round 9
// speedup vs baseline: 2.1810x; 1.2836x over previous
#include <cuda_runtime.h>
#include <cuda_bf16.h>
#include <cstdint>

#define HIDDEN    450
#define DEPTH     6
#define ATOM_FDIM 35
#define BOND_FDIM 5
#define MAX_NB    15
#define N_ATOMS   20000
#define N_BONDS   40000
#define N_MESS    16000
#define N_MOLS    1000
#define BOND_IN   (ATOM_FDIM + BOND_FDIM)   // 40
#define AIN       (ATOM_FDIM + HIDDEN)      // 485

// split-bf16 geometry: A'=[Ah|Al|Ah], B'=[Bh|Bh|Bl]
#define KP     1408              // pad(3*450) in 64s, 22 chunks
#define KP2    1472              // pad(3*485) in 64s, 23 chunks
#define KCH    64
#define WROWS  512               // padded B' rows

// ---------------- scratch (device globals; no runtime allocation) ----------
__device__ float          g_binput[(size_t)N_BONDS * HIDDEN];
__device__ float          g_msg   [(size_t)N_BONDS * HIDDEN];
__device__ __nv_bfloat16  g_neiB  [(size_t)N_BONDS * KP];     // split A' (bonds)
__device__ __nv_bfloat16  g_WB    [(size_t)WROWS * KP];       // split B' (W_h)
__device__ __nv_bfloat16  g_ainB  [(size_t)N_ATOMS * KP2];    // split A' (atoms)
__device__ __nv_bfloat16  g_WoB   [(size_t)WROWS * KP2];      // split B' (W_o)
__device__ float          g_hid   [(size_t)N_ATOMS * HIDDEN];
__device__ float          g_cnt   [N_MOLS];

// ---------------- PTX helpers (baseline sm_103-legal only) ------------------
__device__ __forceinline__ uint32_t smem_u32(const void* p) {
    uint32_t a;
    asm("{ .reg .u64 t; cvta.to.shared.u64 t, %1; cvt.u32.u64 %0, t; }"
        : "=r"(a) : "l"(p));
    return a;
}
#define SWZ128(off) ((off) ^ (((off) >> 3) & 0x70))
#define CP_ASYNC16(dst, src) \
    asm volatile("cp.async.cg.shared.global [%0], [%1], 16;" :: "r"(dst), "l"(src))
#define CP_COMMIT() asm volatile("cp.async.commit_group;" ::: "memory")
#define CP_WAIT(n)  asm volatile("cp.async.wait_group %0;" :: "n"(n) : "memory")

__device__ __forceinline__ void ldsm_x4(uint32_t& r0, uint32_t& r1,
                                        uint32_t& r2, uint32_t& r3, uint32_t a) {
    asm volatile("ldmatrix.sync.aligned.m8n8.x4.shared.b16 {%0,%1,%2,%3}, [%4];"
                 : "=r"(r0), "=r"(r1), "=r"(r2), "=r"(r3) : "r"(a));
}
__device__ __forceinline__ void mma_bf16(float* d, const uint32_t* a,
                                         uint32_t b0, uint32_t b1) {
    asm volatile("mma.sync.aligned.m16n8k16.row.col.f32.bf16.bf16.f32 "
                 "{%0,%1,%2,%3}, {%4,%5,%6,%7}, {%8,%9}, {%0,%1,%2,%3};"
                 : "+f"(d[0]), "+f"(d[1]), "+f"(d[2]), "+f"(d[3])
                 : "r"(a[0]), "r"(a[1]), "r"(a[2]), "r"(a[3]), "r"(b0), "r"(b1));
}

// ---------------- HMMA split-bf16 GEMM: C = relu(A'B'^T + add) --------------
#define CHUNK_A_BYTES (128 * KCH * 2)               // 16 KB
#define CHUNK_B_BYTES (256 * KCH * 2)               // 32 KB
#define STAGE_BYTES   (CHUNK_A_BYTES + CHUNK_B_BYTES)
#define SMEM_GEMM     (2 * STAGE_BYTES)             // 96 KB

template <int KPAD, int ADDMODE>
__global__ __launch_bounds__(512, 1)
void gemm_hmma_relu(const __nv_bfloat16* __restrict__ A,
                    const __nv_bfloat16* __restrict__ B,
                    const float* __restrict__ add,
                    float* __restrict__ C, int M)
{
    constexpr int NCH = KPAD / KCH;
    extern __shared__ char smem[];
    const uint32_t sb = smem_u32(smem);
    const int tid  = threadIdx.x;
    const int lane = tid & 31, warp = tid >> 5;
    const int wm = warp & 3, wn = warp >> 2;
    const int bm = blockIdx.y * 128, n0 = blockIdx.x * 256;

    auto issue = [&](int c, int b) {
        uint32_t abase = sb + b * STAGE_BYTES;
        uint32_t bbase = abase + CHUNK_A_BYTES;
#pragma unroll
        for (int i = 0; i < 2; i++) {
            int idx = tid + i * 512;
            int r = idx >> 3, q = idx & 7;
            int m = bm + r;
            uint32_t dst = abase + SWZ128((uint32_t)(r * 128 + q * 16));
            if (m < M) {
                CP_ASYNC16(dst, A + (size_t)m * KPAD + c * KCH + q * 8);
            } else {
                float4 z = make_float4(0.f, 0.f, 0.f, 0.f);
                *(float4*)(smem + (dst - sb)) = z;
            }
        }
#pragma unroll
        for (int i = 0; i < 4; i++) {
            int idx = tid + i * 512;
            int r = idx >> 3, q = idx & 7;
            uint32_t dst = bbase + SWZ128((uint32_t)(r * 128 + q * 16));
            CP_ASYNC16(dst, B + (size_t)(n0 + r) * KPAD + c * KCH + q * 8);
        }
        CP_COMMIT();
    };

    float acc[2][8][4];
#pragma unroll
    for (int f = 0; f < 2; f++)
#pragma unroll
        for (int j = 0; j < 8; j++)
#pragma unroll
            for (int q = 0; q < 4; q++) acc[f][j][q] = 0.f;

    issue(0, 0);

    for (int c = 0; c < NCH; c++) {
        const int b = c & 1;
        if (c + 1 < NCH) { issue(c + 1, b ^ 1); CP_WAIT(1); }
        else             { CP_WAIT(0); }
        __syncthreads();

        const uint32_t abase = sb + b * STAGE_BYTES;
        const uint32_t bbase = abase + CHUNK_A_BYTES;
#pragma unroll
        for (int s = 0; s < 4; s++) {
            uint32_t af[2][4];
#pragma unroll
            for (int f = 0; f < 2; f++) {
                int row = wm * 32 + f * 16 + (lane & 7) + (((lane >> 3) & 1) << 3);
                int kb  = s * 32 + (((lane >> 4) & 1) << 4);
                ldsm_x4(af[f][0], af[f][1], af[f][2], af[f][3],
                        abase + SWZ128((uint32_t)(row * 128 + kb)));
            }
            uint32_t bf[8][2];
#pragma unroll
            for (int jj = 0; jj < 4; jj++) {
                int row = wn * 64 + jj * 16 + (lane & 7) + (((lane >> 4) & 1) << 3);
                int kb  = s * 32 + (((lane >> 3) & 1) << 4);
                uint32_t r0, r1, r2, r3;
                ldsm_x4(r0, r1, r2, r3, bbase + SWZ128((uint32_t)(row * 128 + kb)));
                bf[jj * 2][0] = r0;     bf[jj * 2][1] = r1;
                bf[jj * 2 + 1][0] = r2; bf[jj * 2 + 1][1] = r3;
            }
#pragma unroll
            for (int f = 0; f < 2; f++)
#pragma unroll
                for (int j = 0; j < 8; j++)
                    mma_bf16(acc[f][j], af[f], bf[j][0], bf[j][1]);
        }
        __syncthreads();
    }

#pragma unroll
    for (int f = 0; f < 2; f++) {
        int mrow = bm + wm * 32 + f * 16 + (lane >> 2);
#pragma unroll
        for (int half = 0; half < 2; half++) {
            int m = mrow + half * 8;
            if (m >= M) continue;
#pragma unroll
            for (int j = 0; j < 8; j++) {
                int n = n0 + wn * 64 + j * 8 + (lane & 3) * 2;
                if (n >= HIDDEN) continue;
                float2 ad;
                if (ADDMODE == 1) ad = *(const float2*)(add + (size_t)m * HIDDEN + n);
                else              ad = *(const float2*)(add + n);
                float2 o;
                o.x = fmaxf(acc[f][j][half * 2 + 0] + ad.x, 0.f);
                o.y = fmaxf(acc[f][j][half * 2 + 1] + ad.y, 0.f);
                *(float2*)(C + (size_t)m * HIDDEN + n) = o;
            }
        }
    }
}

// ---------------- W (fp32 [HIDDEN, K]) -> split-bf16 B' [Bh|Bh|Bl] ----------
template <int K, int KPAD>
__global__ void convert_W(const float* __restrict__ W, __nv_bfloat16* __restrict__ WB)
{
    int idx = blockIdx.x * blockDim.x + threadIdx.x;
    if (idx >= WROWS * KPAD) return;
    int n = idx / KPAD, k = idx % KPAD;
    __nv_bfloat16 out = __float2bfloat16(0.f);
    if (n < HIDDEN) {
        if (k < K) out = __float2bfloat16(W[(size_t)n * K + k]);
        else if (k < 2 * K) out = __float2bfloat16(W[(size_t)n * K + (k - K)]);
        else if (k < 3 * K) {
            float w = W[(size_t)n * K + (k - 2 * K)];
            float hi = __bfloat162float(__float2bfloat16(w));
            out = __float2bfloat16(w - hi);
        }
    }
    WB[idx] = out;
}

// ---------------- warp-per-bond gather-sum -> split-bf16 A' -----------------
// 8 warps/CTA, 1 bond per warp. Pointers broadcast by shfl; no block sync.
__global__ __launch_bounds__(256)
void gather_bonds(const int* __restrict__ bgraph,
                  const float* __restrict__ tree,
                  const float* __restrict__ gmsg,
                  __nv_bfloat16* __restrict__ neiB)
{
    const int b    = blockIdx.x * 8 + (threadIdx.x >> 5);
    const int lane = threadIdx.x & 31;
    if (b >= N_BONDS) return;

    int j = 0;
    if (lane < MAX_NB) j = bgraph[(size_t)b * MAX_NB + lane];
    const float* pl = (j < N_MESS) ? (tree + (size_t)j * HIDDEN)
                                   : (gmsg + (size_t)(j - N_MESS) * HIDDEN);
    unsigned long long pv = (unsigned long long)pl;
    const float* ptr[MAX_NB];
#pragma unroll
    for (int k = 0; k < MAX_NB; k++)
        ptr[k] = (const float*)__shfl_sync(0xffffffffu, pv, k);

    __nv_bfloat16* row = neiB + (size_t)b * KP;
#pragma unroll
    for (int q = 0; q < 8; q++) {
        int h2 = q * 32 + lane;
        if (h2 < HIDDEN / 2) {
            float2 s = make_float2(0.f, 0.f);
#pragma unroll
            for (int k = 0; k < MAX_NB; k++) {
                float2 v = *(const float2*)(ptr[k] + 2 * h2);
                s.x += v.x; s.y += v.y;
            }
            __nv_bfloat16 h0 = __float2bfloat16(s.x), h1 = __float2bfloat16(s.y);
            __nv_bfloat16 l0 = __float2bfloat16(s.x - __bfloat162float(h0));
            __nv_bfloat16 l1 = __float2bfloat16(s.y - __bfloat162float(h1));
            __nv_bfloat162 hi; hi.x = h0; hi.y = h1;
            __nv_bfloat162 lo; lo.x = l0; lo.y = l1;
            *(__nv_bfloat162*)(row + 2 * h2)              = hi;  // Ah
            *(__nv_bfloat162*)(row + HIDDEN + 2 * h2)     = lo;  // Al
            *(__nv_bfloat162*)(row + 2 * HIDDEN + 2 * h2) = hi;  // Ah
        }
    }
    // zero tail 1350..1407 (58 bf16 = 29 bf16x2, element 1350 is even)
    if (lane < 29) {
        __nv_bfloat162 z; z.x = __float2bfloat16(0.f); z.y = z.x;
        *(__nv_bfloat162*)(row + 3 * HIDDEN + 2 * lane) = z;
    }
}

// ---------------- warp-per-atom gather + concat -> split-bf16 A'2 -----------
__global__ __launch_bounds__(256)
void gather_atoms(const int* __restrict__ agraph,
                  const float* __restrict__ fatoms,
                  const float* __restrict__ tree,
                  const float* __restrict__ gmsg,
                  __nv_bfloat16* __restrict__ ainB)
{
    const int a    = blockIdx.x * 8 + (threadIdx.x >> 5);
    const int lane = threadIdx.x & 31;
    if (a >= N_ATOMS) return;

    int j = 0;
    if (lane < MAX_NB) j = agraph[(size_t)a * MAX_NB + lane];
    const float* pl = (j < N_MESS) ? (tree + (size_t)j * HIDDEN)
                                   : (gmsg + (size_t)(j - N_MESS) * HIDDEN);
    unsigned long long pv = (unsigned long long)pl;
    const float* ptr[MAX_NB];
#pragma unroll
    for (int k = 0; k < MAX_NB; k++)
        ptr[k] = (const float*)__shfl_sync(0xffffffffu, pv, k);

    __nv_bfloat16* row = ainB + (size_t)a * KP2;
    // fatoms part: 35 elements
#pragma unroll
    for (int p = 0; p < 2; p++) {
        int h = p * 32 + lane;
        if (h < ATOM_FDIM) {
            float v = fatoms[(size_t)a * ATOM_FDIM + h];
            __nv_bfloat16 hi = __float2bfloat16(v);
            __nv_bfloat16 lo = __float2bfloat16(v - __bfloat162float(hi));
            row[h] = hi; row[AIN + h] = lo; row[2 * AIN + h] = hi;
        }
    }
    // gathered part: 225 float2
#pragma unroll
    for (int q = 0; q < 8; q++) {
        int h2 = q * 32 + lane;
        if (h2 < HIDDEN / 2) {
            float2 s = make_float2(0.f, 0.f);
#pragma unroll
            for (int k = 0; k < MAX_NB; k++) {
                float2 v = *(const float2*)(ptr[k] + 2 * h2);
                s.x += v.x; s.y += v.y;
            }
            int h = ATOM_FDIM + 2 * h2;
            __nv_bfloat16 h0 = __float2bfloat16(s.x), h1 = __float2bfloat16(s.y);
            __nv_bfloat16 l0 = __float2bfloat16(s.x - __bfloat162float(h0));
            __nv_bfloat16 l1 = __float2bfloat16(s.y - __bfloat162float(h1));
            row[h]           = h0; row[h + 1]           = h1;
            row[AIN + h]     = l0; row[AIN + h + 1]     = l1;
            row[2 * AIN + h] = h0; row[2 * AIN + h + 1] = h1;
        }
    }
    // zero tail 1455..1471 (17 bf16)
    if (lane < 17) row[3 * AIN + lane] = __float2bfloat16(0.f);
}

// ---------------- fp32 SIMT GEMM (gemm0 only: K=40) -------------------------
#define BM 128
#define BN 128
#define BK 16
#define SPITCH 132

__global__ __launch_bounds__(256, 2)
void gemm_nt0(const float* __restrict__ A, const float* __restrict__ W,
              float* __restrict__ C, float* __restrict__ C2,
              int M, int N, int K)
{
    __shared__ float sA[2][BK * SPITCH];
    __shared__ float sB[2][BK * SPITCH];
    const int bm = blockIdx.y * BM, bn = blockIdx.x * BN;
    const int tid = threadIdx.x, tx = tid & 15, ty = tid >> 4;

    float acc[8][8];
#pragma unroll
    for (int i = 0; i < 8; i++)
#pragma unroll
        for (int j = 0; j < 8; j++) acc[i][j] = 0.f;

    const int ntiles = (K + BK - 1) / BK;
    float ar[8], br[8];
#pragma unroll
    for (int i = 0; i < 8; i++) {
        int idx = tid + i * 256, r = idx >> 4, kk = idx & 15;
        int m = bm + r;
        ar[i] = (m < M && kk < K) ? A[(size_t)m * K + kk] : 0.f;
        int n = bn + r;
        br[i] = (n < N && kk < K) ? W[(size_t)n * K + kk] : 0.f;
    }
#pragma unroll
    for (int i = 0; i < 8; i++) {
        int idx = tid + i * 256, r = idx >> 4, kk = idx & 15;
        sA[0][kk * SPITCH + r] = ar[i];
        sB[0][kk * SPITCH + r] = br[i];
    }
    __syncthreads();

    int buf = 0;
    for (int t = 0; t < ntiles; t++) {
        if (t + 1 < ntiles) {
            int k0 = (t + 1) * BK;
#pragma unroll
            for (int i = 0; i < 8; i++) {
                int idx = tid + i * 256, r = idx >> 4, kk = idx & 15;
                int m = bm + r, k = k0 + kk;
                ar[i] = (m < M && k < K) ? A[(size_t)m * K + k] : 0.f;
                int n = bn + r;
                br[i] = (n < N && k < K) ? W[(size_t)n * K + k] : 0.f;
            }
        }
        const float* pa = sA[buf];
        const float* pb = sB[buf];
#pragma unroll
        for (int kk = 0; kk < BK; kk++) {
            float a_[8], b_[8];
            *(float4*)&a_[0] = *(const float4*)&pa[kk * SPITCH + ty * 8];
            *(float4*)&a_[4] = *(const float4*)&pa[kk * SPITCH + ty * 8 + 4];
            *(float4*)&b_[0] = *(const float4*)&pb[kk * SPITCH + tx * 8];
            *(float4*)&b_[4] = *(const float4*)&pb[kk * SPITCH + tx * 8 + 4];
#pragma unroll
            for (int i = 0; i < 8; i++)
#pragma unroll
                for (int j = 0; j < 8; j++) acc[i][j] += a_[i] * b_[j];
        }
        if (t + 1 < ntiles) {
            int nb = buf ^ 1;
#pragma unroll
            for (int i = 0; i < 8; i++) {
                int idx = tid + i * 256, r = idx >> 4, kk = idx & 15;
                sA[nb][kk * SPITCH + r] = ar[i];
                sB[nb][kk * SPITCH + r] = br[i];
            }
            __syncthreads();
            buf = nb;
        }
    }
#pragma unroll
    for (int i = 0; i < 8; i++) {
        int m = bm + ty * 8 + i;
        if (m >= M) break;
#pragma unroll
        for (int j = 0; j < 8; j++) {
            int n = bn + tx * 8 + j;
            if (n < N) {
                float v = acc[i][j];
                C [(size_t)m * N + n] = v;
                C2[(size_t)m * N + n] = fmaxf(v, 0.f);
            }
        }
    }
}

// ---------------- segment mean ----------------------------------------------
__global__ void zero_out(float* __restrict__ out, float* __restrict__ cnt)
{
    int i = blockIdx.x * blockDim.x + threadIdx.x;
    if (i < N_MOLS * HIDDEN) out[i] = 0.f;
    if (i < N_MOLS) cnt[i] = 0.f;
}
__global__ void count_mols(const int* __restrict__ mol_ids, float* __restrict__ cnt)
{
    int a = blockIdx.x * blockDim.x + threadIdx.x;
    if (a < N_ATOMS) atomicAdd(&cnt[mol_ids[a]], 1.f);
}
__global__ void accum_mols(const float* __restrict__ hid,
                           const int* __restrict__ mol_ids,
                           float* __restrict__ out)
{
    int a = blockIdx.x;
    int m = mol_ids[a];
    for (int h = threadIdx.x; h < HIDDEN; h += blockDim.x)
        atomicAdd(&out[(size_t)m * HIDDEN + h], hid[(size_t)a * HIDDEN + h]);
}
__global__ void divide_mols(float* __restrict__ out, const float* __restrict__ cnt)
{
    int m = blockIdx.x;
    float inv = 1.f / cnt[m];
    for (int h = threadIdx.x; h < HIDDEN; h += blockDim.x)
        out[(size_t)m * HIDDEN + h] *= inv;
}

// ---------------- launch ------------------------------------------------------
extern "C" void kernel_launch(void* const* d_in, const int* in_sizes, int n_in,
                              void* d_out, int out_size)
{
    const float *fatoms = 0, *fbonds = 0, *tree = 0, *W_i = 0, *W_h = 0, *W_o = 0, *b_o = 0;
    const int *agraph = 0, *bgraph = 0, *mol_ids = 0;
    for (int i = 0; i < n_in; i++) {
        switch (in_sizes[i]) {
            case N_ATOMS * ATOM_FDIM: fatoms  = (const float*)d_in[i]; break;
            case N_BONDS * BOND_IN:   fbonds  = (const float*)d_in[i]; break;
            case N_ATOMS * MAX_NB:    agraph  = (const int*)  d_in[i]; break;
            case N_BONDS * MAX_NB:    bgraph  = (const int*)  d_in[i]; break;
            case N_ATOMS:             mol_ids = (const int*)  d_in[i]; break;
            case N_MESS * HIDDEN:     tree    = (const float*)d_in[i]; break;
            case HIDDEN * BOND_IN:    W_i     = (const float*)d_in[i]; break;
            case HIDDEN * HIDDEN:     W_h     = (const float*)d_in[i]; break;
            case HIDDEN * AIN:        W_o     = (const float*)d_in[i]; break;
            case HIDDEN:              b_o     = (const float*)d_in[i]; break;
            default: break;
        }
    }
    float* out = (float*)d_out;

    static float *p_binput = 0, *p_msg = 0, *p_hid = 0, *p_cnt = 0;
    static __nv_bfloat16 *p_neiB = 0, *p_WB = 0, *p_ainB = 0, *p_WoB = 0;
    if (!p_binput) {
        cudaGetSymbolAddress((void**)&p_binput, g_binput);
        cudaGetSymbolAddress((void**)&p_msg,    g_msg);
        cudaGetSymbolAddress((void**)&p_neiB,   g_neiB);
        cudaGetSymbolAddress((void**)&p_WB,     g_WB);
        cudaGetSymbolAddress((void**)&p_ainB,   g_ainB);
        cudaGetSymbolAddress((void**)&p_WoB,    g_WoB);
        cudaGetSymbolAddress((void**)&p_hid,    g_hid);
        cudaGetSymbolAddress((void**)&p_cnt,    g_cnt);
        cudaFuncSetAttribute(gemm_hmma_relu<KP, 1>,
                             cudaFuncAttributeMaxDynamicSharedMemorySize, SMEM_GEMM);
        cudaFuncSetAttribute(gemm_hmma_relu<KP2, 2>,
                             cudaFuncAttributeMaxDynamicSharedMemorySize, SMEM_GEMM);
    }

    dim3 gB((HIDDEN + BN - 1) / BN, (N_BONDS + BM - 1) / BM);  // (4, 313)
    dim3 gM(2, (N_BONDS + 127) / 128);                         // (2, 313)
    dim3 gM2(2, (N_ATOMS + 127) / 128);                        // (2, 157)

    // 0) weight conversions
    convert_W<HIDDEN, KP ><<<(WROWS * KP  + 255) / 256, 256>>>(W_h, p_WB);
    convert_W<AIN,    KP2><<<(WROWS * KP2 + 255) / 256, 256>>>(W_o, p_WoB);

    // 1) binput = fbonds @ W_i^T ; graph_message = relu(binput)   (fused)
    gemm_nt0<<<gB, 256>>>(fbonds, W_i, p_binput, p_msg, N_BONDS, HIDDEN, BOND_IN);

    // 2) DEPTH-1 message passing iterations (HMMA split-bf16)
    for (int it = 0; it < DEPTH - 1; it++) {
        gather_bonds<<<N_BONDS / 8, 256>>>(bgraph, tree, p_msg, p_neiB);
        gemm_hmma_relu<KP, 1><<<gM, 512, SMEM_GEMM>>>(p_neiB, p_WB, p_binput,
                                                      p_msg, N_BONDS);
    }

    // 3) atom-side gather + concat -> split-bf16 A'2
    gather_atoms<<<N_ATOMS / 8, 256>>>(agraph, fatoms, tree, p_msg, p_ainB);

    // 4) atom_hiddens = relu(ainput @ W_o^T + b_o)   (HMMA split-bf16)
    gemm_hmma_relu<KP2, 2><<<gM2, 512, SMEM_GEMM>>>(p_ainB, p_WoB, b_o,
                                                    p_hid, N_ATOMS);

    // 5) segment mean over molecules
    zero_out<<<(N_MOLS * HIDDEN + 255) / 256, 256>>>(out, p_cnt);
    count_mols<<<(N_ATOMS + 255) / 256, 256>>>(mol_ids, p_cnt);
    accum_mols<<<N_ATOMS, 128>>>(p_hid, mol_ids, out);
    divide_mols<<<N_MOLS, 128>>>(out, p_cnt);
}